// round 5
// baseline (speedup 1.0000x reference)
#include <cuda_runtime.h>

#define HDIM    128
#define MT      64          // edges per CTA
#define THREADS 256
#define HS_LD   132         // Hi/Hj row stride (floats), pad for banks + f4 align
#define X1_LD   260         // X1 row stride (floats)
#define KC1     16          // k-chunk for layer 1 (per 128-block)
#define KC2     32          // k-chunk for layer 2

// SMEM layout (floats):
//  Hi  [64][132]        =  8448
//  Hj  [64][132]        =  8448
//  X1  [64][260]        = 16640
//  Ws  [max stage]      = 16384   (layer1: 4*16*256 ; layer2: 32*128=4096 fits)
//  W3s [256] + b3s[8]   =   264
#define SMEM_FLOATS (8448 + 8448 + 16640 + 16384 + 264)
#define SMEM_BYTES  (SMEM_FLOATS * 4)

__device__ __forceinline__ unsigned long long pack2(float x) {
    unsigned long long r;
    asm("mov.b64 %0, {%1, %1};" : "=l"(r) : "f"(x));
    return r;
}
__device__ __forceinline__ unsigned long long pack2f(float lo, float hi) {
    unsigned long long r;
    asm("mov.b64 %0, {%1, %2};" : "=l"(r) : "f"(lo), "f"(hi));
    return r;
}
__device__ __forceinline__ void fma2(unsigned long long& d, unsigned long long a, unsigned long long b) {
    asm("fma.rn.f32x2 %0, %1, %2, %0;" : "+l"(d) : "l"(a), "l"(b));
}
__device__ __forceinline__ float2 unpack2(unsigned long long v) {
    float2 f;
    asm("mov.b64 {%0, %1}, %2;" : "=f"(f.x), "=f"(f.y) : "l"(v));
    return f;
}

__global__ __launch_bounds__(THREADS, 1)
void entity_linker_kernel(
    const float* __restrict__ node,
    const int*   __restrict__ src,
    const int*   __restrict__ dst,
    const float* __restrict__ W1, const float* __restrict__ b1,
    const float* __restrict__ W2, const float* __restrict__ b2,
    const float* __restrict__ W3, const float* __restrict__ b3,
    float* __restrict__ out, int E)
{
    extern __shared__ float smem[];
    float* Hi  = smem;
    float* Hj  = Hi + MT * HS_LD;
    float* X1  = Hj + MT * HS_LD;
    float* Ws  = X1 + MT * X1_LD;
    float* W3s = Ws + 4 * KC1 * 256;
    float* b3s = W3s + 256;

    const int tid = threadIdx.x;
    const int e0  = blockIdx.x * MT;

    // ---- stage W3 / b3 once ----
    if (tid < 256) W3s[tid] = W3[tid];
    if (tid < 2)   b3s[tid] = b3[tid];

    // ---- gather Hi / Hj (clamped for tail tile) ----
    #pragma unroll
    for (int it = 0; it < (MT * 32) / THREADS; it++) {
        int v   = tid + it * THREADS;
        int row = v >> 5;
        int seg = v & 31;
        int e = e0 + row; if (e >= E) e = E - 1;
        int s = src[e];
        int d = dst[e];
        float4 a = *(const float4*)(node + (size_t)s * HDIM + seg * 4);
        float4 b = *(const float4*)(node + (size_t)d * HDIM + seg * 4);
        *(float4*)(Hi + row * HS_LD + seg * 4) = a;
        *(float4*)(Hj + row * HS_LD + seg * 4) = b;
    }
    __syncthreads();

    const int tx = tid & 15;      // n-dim threads
    const int ty = tid >> 4;      // m-dim threads
    const int m0 = ty * 4;

    // ======================= Layer 1: [64,512(virt)] @ W1 -> [64,256] =======================
    // Each thread: 4 m-rows x 16 n-cols -> 4x8 packed f32x2 accumulators.
    {
        const int n0 = tx * 16;
        unsigned long long c1[4][8];
        {
            const float4* bp = (const float4*)(b1 + n0);
            #pragma unroll
            for (int q = 0; q < 4; q++) {
                float4 b4 = bp[q];
                unsigned long long p0 = pack2f(b4.x, b4.y);
                unsigned long long p1 = pack2f(b4.z, b4.w);
                #pragma unroll
                for (int i = 0; i < 4; i++) { c1[i][q*2] = p0; c1[i][q*2+1] = p1; }
            }
        }

        for (int kc = 0; kc < HDIM / KC1; kc++) {          // 8 chunks
            // stage 4 blocks x KC1 rows x 256 cols = 16384 floats (4096 f4, 16/thread)
            #pragma unroll
            for (int it = 0; it < 16; it++) {
                int v   = tid + it * THREADS;   // float4 index
                int fl  = v * 4;
                int rr  = fl >> 8;              // row within stage, 0..63
                int col = fl & 255;
                int blk = rr >> 4;              // 0..3
                int kk  = rr & 15;
                int r   = blk * HDIM + kc * KC1 + kk;       // global W1 row
                *(float4*)(Ws + rr * 256 + col) = *(const float4*)(W1 + r * 256 + col);
            }
            __syncthreads();

            #pragma unroll 4
            for (int kk = 0; kk < KC1; kk++) {
                const int k = kc * KC1 + kk;
                unsigned long long A[4][4];
                #pragma unroll
                for (int i = 0; i < 4; i++) {
                    float hi = Hi[(m0 + i) * HS_LD + k];
                    float hj = Hj[(m0 + i) * HS_LD + k];
                    A[i][0] = pack2(hi);
                    A[i][1] = pack2(hj);
                    A[i][2] = pack2(fabsf(hi - hj));
                    A[i][3] = pack2(hi * hj);
                }
                #pragma unroll
                for (int blk = 0; blk < 4; blk++) {
                    const ulonglong2* wp = (const ulonglong2*)(Ws + (blk * KC1 + kk) * 256 + n0);
                    ulonglong2 w01 = wp[0];
                    ulonglong2 w23 = wp[1];
                    ulonglong2 w45 = wp[2];
                    ulonglong2 w67 = wp[3];
                    #pragma unroll
                    for (int i = 0; i < 4; i++) {
                        fma2(c1[i][0], A[i][blk], w01.x);
                        fma2(c1[i][1], A[i][blk], w01.y);
                        fma2(c1[i][2], A[i][blk], w23.x);
                        fma2(c1[i][3], A[i][blk], w23.y);
                        fma2(c1[i][4], A[i][blk], w45.x);
                        fma2(c1[i][5], A[i][blk], w45.y);
                        fma2(c1[i][6], A[i][blk], w67.x);
                        fma2(c1[i][7], A[i][blk], w67.y);
                    }
                }
            }
            __syncthreads();
        }

        // ReLU -> X1 smem
        #pragma unroll
        for (int i = 0; i < 4; i++) {
            #pragma unroll
            for (int q = 0; q < 4; q++) {
                float2 f0 = unpack2(c1[i][q*2]);
                float2 f1 = unpack2(c1[i][q*2+1]);
                float4 r;
                r.x = fmaxf(f0.x, 0.f); r.y = fmaxf(f0.y, 0.f);
                r.z = fmaxf(f1.x, 0.f); r.w = fmaxf(f1.y, 0.f);
                *(float4*)(X1 + (m0 + i) * X1_LD + n0 + q * 4) = r;
            }
        }
    }
    __syncthreads();

    // ======================= Layer 2: [64,256] @ W2 -> [64,128] =======================
    float* X2 = Hi;   // reuse Hi region, stride HS_LD
    {
        const int n0 = tx * 8;
        unsigned long long c2[4][4];
        {
            const float4* bp = (const float4*)(b2 + n0);
            float4 b4a = bp[0], b4b = bp[1];
            unsigned long long p0 = pack2f(b4a.x, b4a.y);
            unsigned long long p1 = pack2f(b4a.z, b4a.w);
            unsigned long long p2 = pack2f(b4b.x, b4b.y);
            unsigned long long p3 = pack2f(b4b.z, b4b.w);
            #pragma unroll
            for (int i = 0; i < 4; i++) { c2[i][0]=p0; c2[i][1]=p1; c2[i][2]=p2; c2[i][3]=p3; }
        }

        for (int kc = 0; kc < 256 / KC2; kc++) {           // 8 chunks
            // stage KC2 x 128 = 4096 floats (1024 f4, 4/thread)
            #pragma unroll
            for (int it = 0; it < 4; it++) {
                int v   = tid + it * THREADS;
                int fl  = v * 4;
                int rr  = fl >> 7;              // 0..31
                int col = fl & 127;
                int r   = kc * KC2 + rr;
                *(float4*)(Ws + rr * 128 + col) = *(const float4*)(W2 + r * 128 + col);
            }
            __syncthreads();

            #pragma unroll 4
            for (int kk = 0; kk < KC2; kk++) {
                const int k = kc * KC2 + kk;
                unsigned long long Ap[4];
                #pragma unroll
                for (int i = 0; i < 4; i++)
                    Ap[i] = pack2(X1[(m0 + i) * X1_LD + k]);
                const ulonglong2* wp = (const ulonglong2*)(Ws + kk * 128 + n0);
                ulonglong2 w01 = wp[0];
                ulonglong2 w23 = wp[1];
                #pragma unroll
                for (int i = 0; i < 4; i++) {
                    fma2(c2[i][0], Ap[i], w01.x);
                    fma2(c2[i][1], Ap[i], w01.y);
                    fma2(c2[i][2], Ap[i], w23.x);
                    fma2(c2[i][3], Ap[i], w23.y);
                }
            }
            __syncthreads();
        }

        // ReLU -> X2 smem (over old Hi region; layer1 fully done)
        #pragma unroll
        for (int i = 0; i < 4; i++) {
            float2 f0 = unpack2(c2[i][0]);
            float2 f1 = unpack2(c2[i][1]);
            float2 f2 = unpack2(c2[i][2]);
            float2 f3 = unpack2(c2[i][3]);
            float4 ra, rb;
            ra.x = fmaxf(f0.x, 0.f); ra.y = fmaxf(f0.y, 0.f);
            ra.z = fmaxf(f1.x, 0.f); ra.w = fmaxf(f1.y, 0.f);
            rb.x = fmaxf(f2.x, 0.f); rb.y = fmaxf(f2.y, 0.f);
            rb.z = fmaxf(f3.x, 0.f); rb.w = fmaxf(f3.y, 0.f);
            *(float4*)(X2 + (m0 + i) * HS_LD + n0)     = ra;
            *(float4*)(X2 + (m0 + i) * HS_LD + n0 + 4) = rb;
        }
    }
    __syncthreads();

    // ======================= Layer 3: [64,128] @ W3 -> [64,2] =======================
    if (tid < MT * 2) {
        int m = tid >> 1;
        int c = tid & 1;
        float sum = b3s[c];
        const float* x2r = X2 + m * HS_LD;
        #pragma unroll 8
        for (int k = 0; k < HDIM; k++)
            sum += x2r[k] * W3s[k * 2 + c];
        int e = e0 + m;
        if (e < E) out[e * 2 + c] = sum;
    }
}

extern "C" void kernel_launch(void* const* d_in, const int* in_sizes, int n_in,
                              void* d_out, int out_size) {
    const float* node = (const float*)d_in[0];
    const int*   src  = (const int*)  d_in[1];
    const int*   dst  = (const int*)  d_in[2];
    const float* W1   = (const float*)d_in[3];
    const float* b1   = (const float*)d_in[4];
    const float* W2   = (const float*)d_in[5];
    const float* b2   = (const float*)d_in[6];
    const float* W3   = (const float*)d_in[7];
    const float* b3   = (const float*)d_in[8];
    float* out = (float*)d_out;
    (void)n_in; (void)out_size;

    int E = in_sizes[1];   // src element count = number of edges

    cudaFuncSetAttribute(entity_linker_kernel,
                         cudaFuncAttributeMaxDynamicSharedMemorySize, SMEM_BYTES);

    int grid = (E + MT - 1) / MT;
    entity_linker_kernel<<<grid, THREADS, SMEM_BYTES>>>(
        node, src, dst, W1, b1, W2, b2, W3, b3, out, E);
}

// round 6
// speedup vs baseline: 4.3692x; 4.3692x over previous
#include <cuda_runtime.h>

#define HDIM    128
#define MT      64          // edges per CTA
#define THREADS 256
#define HS_LD   132         // Hi/Hj/X2 row stride (floats)
#define X1_LD   260         // X1 row stride (floats)

// Ws: double buffer, 8192 floats each (32KB). Layer1 chunk: 4 blk x 8 kk x 256.
// Layer2 chunk: 64 rows x 128.
#define WS_HALF 8192
// SMEM floats: Hi 8448 + Hj 8448 + X1 16640 + Ws 16384 + W3s 256 + b3s 8
#define SMEM_FLOATS (8448 + 8448 + 16640 + 16384 + 256 + 8)
#define SMEM_BYTES  (SMEM_FLOATS * 4)

__device__ __forceinline__ unsigned long long pack2(float x) {
    unsigned long long r;
    asm("mov.b64 %0, {%1, %1};" : "=l"(r) : "f"(x));
    return r;
}
__device__ __forceinline__ unsigned long long pack2f(float lo, float hi) {
    unsigned long long r;
    asm("mov.b64 %0, {%1, %2};" : "=l"(r) : "f"(lo), "f"(hi));
    return r;
}
__device__ __forceinline__ void fma2(unsigned long long& d, unsigned long long a, unsigned long long b) {
    asm("fma.rn.f32x2 %0, %1, %2, %0;" : "+l"(d) : "l"(a), "l"(b));
}
__device__ __forceinline__ float2 unpack2(unsigned long long v) {
    float2 f;
    asm("mov.b64 {%0, %1}, %2;" : "=f"(f.x), "=f"(f.y) : "l"(v));
    return f;
}
__device__ __forceinline__ void cp_async16(float* s, const float* g) {
    unsigned sa = (unsigned)__cvta_generic_to_shared(s);
    asm volatile("cp.async.cg.shared.global [%0], [%1], 16;\n" :: "r"(sa), "l"(g) : "memory");
}
__device__ __forceinline__ void cp_commit() {
    asm volatile("cp.async.commit_group;\n" ::: "memory");
}
template <int N>
__device__ __forceinline__ void cp_wait() {
    asm volatile("cp.async.wait_group %0;\n" :: "n"(N) : "memory");
}

// Issue async copy of weight chunk c into Ws half (c&1).
// c in [0,16): W1 chunk (4 blocks x 8 k-rows x 256 cols).
// c in [16,20): W2 chunk (64 k-rows x 128 cols).
__device__ __forceinline__ void issue_chunk(int c, float* Ws,
                                            const float* __restrict__ W1,
                                            const float* __restrict__ W2,
                                            int tid) {
    float* dstb = Ws + (c & 1) * WS_HALF;
    if (c < 16) {
        #pragma unroll
        for (int it = 0; it < 8; it++) {
            int v   = tid + it * THREADS;   // float4 index
            int fl  = v * 4;
            int rr  = fl >> 8;              // 0..31 staged row
            int col = fl & 255;
            int blk = rr >> 3;
            int kk  = rr & 7;
            const float* g = W1 + (size_t)(blk * HDIM + c * 8 + kk) * 256 + col;
            cp_async16(dstb + rr * 256 + col, g);
        }
    } else {
        int c2 = c - 16;
        #pragma unroll
        for (int it = 0; it < 8; it++) {
            int v   = tid + it * THREADS;
            int fl  = v * 4;
            int rr  = fl >> 7;              // 0..63 staged row
            int col = fl & 127;
            const float* g = W2 + (size_t)(c2 * 64 + rr) * 128 + col;
            cp_async16(dstb + rr * 128 + col, g);
        }
    }
    cp_commit();
}

__global__ __launch_bounds__(THREADS, 1)
void entity_linker_kernel(
    const float* __restrict__ node,
    const int*   __restrict__ src,
    const int*   __restrict__ dst,
    const float* __restrict__ W1, const float* __restrict__ b1,
    const float* __restrict__ W2, const float* __restrict__ b2,
    const float* __restrict__ W3, const float* __restrict__ b3,
    float* __restrict__ out, int E)
{
    extern __shared__ float smem[];
    float* Hi  = smem;
    float* Hj  = Hi + MT * HS_LD;
    float* X1  = Hj + MT * HS_LD;
    float* Ws  = X1 + MT * X1_LD;
    float* W3s = Ws + 2 * WS_HALF;     // [2][128] col-major: W3s[c*128+k]
    float* b3s = W3s + 256;

    const int tid = threadIdx.x;
    const int e0  = blockIdx.x * MT;

    // kick off weight chunk 0 ASAP (overlaps the gather)
    issue_chunk(0, Ws, W1, W2, tid);

    // stage W3 (col-major) / b3
    W3s[(tid & 1) * HDIM + (tid >> 1)] = W3[tid];
    if (tid < 2) b3s[tid] = b3[tid];

    // ---- gather Hi / Hj (clamped for tail tile) ----
    #pragma unroll
    for (int it = 0; it < (MT * 32) / THREADS; it++) {
        int v   = tid + it * THREADS;
        int row = v >> 5;
        int seg = v & 31;
        int e = e0 + row; if (e >= E) e = E - 1;
        int s = src[e];
        int d = dst[e];
        float4 a = *(const float4*)(node + (size_t)s * HDIM + seg * 4);
        float4 b = *(const float4*)(node + (size_t)d * HDIM + seg * 4);
        *(float4*)(Hi + row * HS_LD + seg * 4) = a;
        *(float4*)(Hj + row * HS_LD + seg * 4) = b;
    }

    const int tx = tid & 31;          // n-dim: 32 threads
    const int ty = tid >> 5;          // m-dim: 8 warps, warp == one m-group
    const int m0 = ty * 8;
    const int n4 = tx * 4;            // thread's base column (4 consecutive floats)

    // ======================= Layer 1: virtual [64,512] @ W1 -> [64,256] ===================
    // Thread tile: 8 m-rows x 8 n-cols (cols n4..n4+3 and 128+n4..128+n4+3).
    {
        unsigned long long c1[8][4];
        {
            float4 ba = *(const float4*)(b1 + n4);
            float4 bb = *(const float4*)(b1 + 128 + n4);
            unsigned long long p0 = pack2f(ba.x, ba.y);
            unsigned long long p1 = pack2f(ba.z, ba.w);
            unsigned long long p2 = pack2f(bb.x, bb.y);
            unsigned long long p3 = pack2f(bb.z, bb.w);
            #pragma unroll
            for (int i = 0; i < 8; i++) { c1[i][0]=p0; c1[i][1]=p1; c1[i][2]=p2; c1[i][3]=p3; }
        }

        for (int kc = 0; kc < 16; kc++) {
            issue_chunk(kc + 1, Ws, W1, W2, tid);   // prefetch next (chunk 16 == W2 chunk 0)
            cp_wait<1>();                           // chunk kc resident
            __syncthreads();

            const float* Wb = Ws + (kc & 1) * WS_HALF;
            #pragma unroll
            for (int kk = 0; kk < 8; kk++) {
                const int k = kc * 8 + kk;
                unsigned long long A[8][4];
                #pragma unroll
                for (int i = 0; i < 8; i++) {
                    float hi = Hi[(m0 + i) * HS_LD + k];   // uniform addr -> broadcast
                    float hj = Hj[(m0 + i) * HS_LD + k];
                    A[i][0] = pack2(hi);
                    A[i][1] = pack2(hj);
                    A[i][2] = pack2(fabsf(hi - hj));
                    A[i][3] = pack2(hi * hj);
                }
                #pragma unroll
                for (int blk = 0; blk < 4; blk++) {
                    const float* wr = Wb + (blk * 8 + kk) * 256;
                    ulonglong2 w0 = *(const ulonglong2*)(wr + n4);        // lanes contiguous 16B
                    ulonglong2 w1 = *(const ulonglong2*)(wr + 128 + n4);
                    #pragma unroll
                    for (int i = 0; i < 8; i++) {
                        fma2(c1[i][0], A[i][blk], w0.x);
                        fma2(c1[i][1], A[i][blk], w0.y);
                        fma2(c1[i][2], A[i][blk], w1.x);
                        fma2(c1[i][3], A[i][blk], w1.y);
                    }
                }
            }
            __syncthreads();   // before next chunk overwrites this Ws half
        }

        // ReLU -> X1 (per (i,half): lanes store contiguous 16B -> conflict-free)
        #pragma unroll
        for (int i = 0; i < 8; i++) {
            float2 f0 = unpack2(c1[i][0]);
            float2 f1 = unpack2(c1[i][1]);
            float2 f2 = unpack2(c1[i][2]);
            float2 f3 = unpack2(c1[i][3]);
            float4 ra, rb;
            ra.x = fmaxf(f0.x, 0.f); ra.y = fmaxf(f0.y, 0.f);
            ra.z = fmaxf(f1.x, 0.f); ra.w = fmaxf(f1.y, 0.f);
            rb.x = fmaxf(f2.x, 0.f); rb.y = fmaxf(f2.y, 0.f);
            rb.z = fmaxf(f3.x, 0.f); rb.w = fmaxf(f3.y, 0.f);
            *(float4*)(X1 + (m0 + i) * X1_LD + n4)       = ra;
            *(float4*)(X1 + (m0 + i) * X1_LD + 128 + n4) = rb;
        }
    }

    // ======================= Layer 2: [64,256] @ W2 -> [64,128] =======================
    float* X2 = Hi;   // reuse Hi region (stride HS_LD)
    {
        unsigned long long c2[8][2];
        {
            float4 bv = *(const float4*)(b2 + n4);
            unsigned long long p0 = pack2f(bv.x, bv.y);
            unsigned long long p1 = pack2f(bv.z, bv.w);
            #pragma unroll
            for (int i = 0; i < 8; i++) { c2[i][0]=p0; c2[i][1]=p1; }
        }

        for (int c2i = 0; c2i < 4; c2i++) {
            if (c2i < 3) { issue_chunk(17 + c2i, Ws, W1, W2, tid); cp_wait<1>(); }
            else         { cp_wait<0>(); }
            __syncthreads();   // also covers X1 ReLU stores on first iteration

            const float* Wb = Ws + ((16 + c2i) & 1) * WS_HALF;
            #pragma unroll
            for (int kk = 0; kk < 64; kk++) {
                const int k = c2i * 64 + kk;
                ulonglong2 w = *(const ulonglong2*)(Wb + kk * 128 + n4);
                #pragma unroll
                for (int i = 0; i < 8; i++) {
                    unsigned long long Ap = pack2(X1[(m0 + i) * X1_LD + k]);  // broadcast
                    fma2(c2[i][0], Ap, w.x);
                    fma2(c2[i][1], Ap, w.y);
                }
            }
            __syncthreads();
        }

        // ReLU -> X2 (overwrites Hi; layer1 fully consumed)
        #pragma unroll
        for (int i = 0; i < 8; i++) {
            float2 f0 = unpack2(c2[i][0]);
            float2 f1 = unpack2(c2[i][1]);
            float4 r;
            r.x = fmaxf(f0.x, 0.f); r.y = fmaxf(f0.y, 0.f);
            r.z = fmaxf(f1.x, 0.f); r.w = fmaxf(f1.y, 0.f);
            *(float4*)(X2 + (m0 + i) * HS_LD + n4) = r;
        }
    }
    __syncthreads();

    // ======================= Layer 3: [64,128] @ W3 -> [64,2] =======================
    if (tid < MT * 2) {
        int m = tid >> 1;
        int c = tid & 1;
        const float* x2r = X2 + m * HS_LD;
        const float* w3c = W3s + c * HDIM;
        float4 acc = {0.f, 0.f, 0.f, 0.f};
        #pragma unroll
        for (int k = 0; k < HDIM; k += 4) {
            float4 xv = *(const float4*)(x2r + k);
            float4 wv = *(const float4*)(w3c + k);
            acc.x += xv.x * wv.x; acc.y += xv.y * wv.y;
            acc.z += xv.z * wv.z; acc.w += xv.w * wv.w;
        }
        float sum = b3s[c] + (acc.x + acc.y) + (acc.z + acc.w);
        int e = e0 + m;
        if (e < E) out[e * 2 + c] = sum;
    }
}

extern "C" void kernel_launch(void* const* d_in, const int* in_sizes, int n_in,
                              void* d_out, int out_size) {
    const float* node = (const float*)d_in[0];
    const int*   src  = (const int*)  d_in[1];
    const int*   dst  = (const int*)  d_in[2];
    const float* W1   = (const float*)d_in[3];
    const float* b1   = (const float*)d_in[4];
    const float* W2   = (const float*)d_in[5];
    const float* b2   = (const float*)d_in[6];
    const float* W3   = (const float*)d_in[7];
    const float* b3   = (const float*)d_in[8];
    float* out = (float*)d_out;
    (void)n_in; (void)out_size;

    int E = in_sizes[1];   // src element count = number of edges

    cudaFuncSetAttribute(entity_linker_kernel,
                         cudaFuncAttributeMaxDynamicSharedMemorySize, SMEM_BYTES);

    int grid = (E + MT - 1) / MT;
    entity_linker_kernel<<<grid, THREADS, SMEM_BYTES>>>(
        node, src, dst, W1, b1, W2, b2, W3, b3, out, E);
}